// round 17
// baseline (speedup 1.0000x reference)
#include <cuda_runtime.h>
#include <cuda_fp16.h>
#include <cstdint>

#define N_NODES 50000
#define N_EDGES 800000
#define SCAN_BLOCKS ((N_NODES + 255) / 256)   // 196
#define M_TILES (N_NODES / 16)                // 3125, exact
#define N_PAIRS ((M_TILES + 1) / 2)           // 1563 m-tile pairs
#define P_CTAS 148                            // persistent CTAs, 1 per SM

// ---------------- scratch (static __device__, zero-initialized at load) ----------------
__device__ float    g_Q[N_NODES * 128];
// interleaved fp16 K/V: per node 128 words; lane l owns words 4l..4l+3 = {K2l,K2l+1,V2l,V2l+1}
__device__ uint32_t g_KV[N_NODES * 128];
__device__ int      g_row_off[N_NODES + 1];
__device__ int      g_cnt[N_NODES];           // counts -> cursors; re-zeroed by aggregate
__device__ int      g_esrc[N_EDGES];          // src node id per CSR slot
__device__ int      g_part[SCAN_BLOCKS];

// fp16 A fragments: [mtile][ks][lane] -> uint4 {a0,a1,a2,a3} (half2 words); lane-contiguous
__device__ uint4 g_hf[M_TILES * 8 * 32];
// fp16 B fragments: [z][ks][w][pair][lane]; pair outside lane => lane-contiguous 128B loads
__device__ uint4 g_wf4[3][8][4][2][32];       // 6144 uint4 = 98304 B

__device__ __forceinline__ uint32_t pack_h2(float a, float b) {
    __half2 h = __floats2half2_rn(a, b);
    return *reinterpret_cast<uint32_t*>(&h);
}

// ---------------- prep: z=0 A-fragment fp16 pack of h, z=1 edge count, z=2 B fragments ----------------
// grid (3125, 1, 3) x 256 threads
__global__ void __launch_bounds__(256) prep_kernel(
    const float* __restrict__ h, const int* __restrict__ dst,
    const float* __restrict__ Wq, const float* __restrict__ Wk, const float* __restrict__ Wv)
{
    const int z = blockIdx.z;
    const int tid = blockIdx.x * 256 + threadIdx.x;   // < 800000

    if (z == 0) {
        int lane = tid & 31;
        int ks   = (tid >> 5) & 7;
        int mt   = tid >> 8;                 // < 3125
        int g = lane >> 2, t = lane & 3;
        int r0 = mt * 16 + g;
        int r1 = r0 + 8;
        int base = ks * 16 + 2 * t;
        float2 f0 = *reinterpret_cast<const float2*>(&h[r0 * 128 + base]);       // a0
        float2 f2 = *reinterpret_cast<const float2*>(&h[r0 * 128 + base + 8]);   // a2
        float2 f1 = *reinterpret_cast<const float2*>(&h[r1 * 128 + base]);       // a1
        float2 f3 = *reinterpret_cast<const float2*>(&h[r1 * 128 + base + 8]);   // a3
        uint4 a;
        a.x = pack_h2(f0.x, f0.y);
        a.y = pack_h2(f1.x, f1.y);
        a.z = pack_h2(f2.x, f2.y);
        a.w = pack_h2(f3.x, f3.y);
        g_hf[tid] = a;
    } else if (z == 1) {
        if (tid < N_EDGES) atomicAdd(&g_cnt[dst[tid]], 1);
    } else {
        if (tid >= 3 * 8 * 16 * 32) return;
        int lane = tid & 31;
        int nt   = (tid >> 5) & 15;
        int ks   = (tid >> 9) & 7;
        int zz   = tid >> 12;
        const float* W = (zz == 0) ? Wq : (zz == 1) ? Wk : Wv;
        int g = lane >> 2, t = lane & 3;
        int n  = nt * 8 + g;
        int kb = ks * 16 + t * 2;
        uint2 b;
        b.x = pack_h2(W[(kb + 0) * 128 + n], W[(kb + 1) * 128 + n]);
        b.y = pack_h2(W[(kb + 8) * 128 + n], W[(kb + 9) * 128 + n]);
        int w = nt >> 2, p = (nt >> 1) & 1, which = nt & 1;
        reinterpret_cast<uint2*>(&g_wf4[zz][ks][w][p][lane])[which] = b;
    }
}

// ---------------- persistent fused GEMM (warps 0-3) + scatter (warps 4-7) ----------------
__device__ __forceinline__ void mma_f16(float& c0, float& c1, float& c2, float& c3,
                                        uint32_t a0, uint32_t a1, uint32_t a2, uint32_t a3,
                                        uint32_t b0, uint32_t b1)
{
    asm volatile(
        "mma.sync.aligned.m16n8k16.row.col.f32.f16.f16.f32 "
        "{%0,%1,%2,%3},{%4,%5,%6,%7},{%8,%9},{%0,%1,%2,%3};"
        : "+f"(c0), "+f"(c1), "+f"(c2), "+f"(c3)
        : "r"(a0), "r"(a1), "r"(a2), "r"(a3), "r"(b0), "r"(b1));
}

#define SMEM_B_BYTES 98304      // full B fragment table, staged once per CTA

__global__ void __launch_bounds__(256, 1) gemm_scatter(
    const float* __restrict__ bq, const float* __restrict__ bk, const float* __restrict__ bv,
    const int* __restrict__ src, const int* __restrict__ dst)
{
    extern __shared__ uint4 s_wf[];          // [3][8][4][2][32] flattened, 6144 uint4
    const int tid  = threadIdx.x;
    const int wid  = tid >> 5;
    const int lane = tid & 31;

    if (wid >= 4) {
        // ---- scatter half: 148*128 lanes, stride loop over 800k edges ----
        int t = blockIdx.x * 128 + (tid - 128);
        for (int e = t; e < N_EDGES; e += P_CTAS * 128) {
            int p = atomicAdd(&g_cnt[dst[e]], 1);
            g_esrc[p] = src[e];
        }
        return;
    }

    // ---- GEMM half (threads 0-127): stage B table once, then loop m-tile pairs ----
    {
        const uint4* bsrc = reinterpret_cast<const uint4*>(g_wf4);
        #pragma unroll
        for (int i = 0; i < 48; i++) s_wf[tid + i * 128] = bsrc[tid + i * 128];
    }
    asm volatile("bar.sync 1, 128;" ::: "memory");

    const int w = wid;
    const int g = lane >> 2;
    const int t = lane & 3;

    // smem B pointers for this warp: [z][ks][w][pair][lane]
    //   index = ((z*8 + ks)*4 + w)*64 + pair*32 + lane
    float bias0[3][4][2];
    #pragma unroll
    for (int z = 0; z < 3; z++) {
        const float* bias = (z == 0) ? bq : (z == 1) ? bk : bv;
        #pragma unroll
        for (int nt = 0; nt < 4; nt++) {
            int col = (w * 4 + nt) * 8 + t * 2;
            bias0[z][nt][0] = bias[col];
            bias0[z][nt][1] = bias[col + 1];
        }
    }

    for (int pair = blockIdx.x; pair < N_PAIRS; pair += P_CTAS) {
        const int mt0  = pair * 2;
        const int mt1  = mt0 + 1;
        const bool has2 = (mt1 < M_TILES);
        const int mt1c = has2 ? mt1 : mt0;

        float c0[3][4][4], c1[3][4][4];
        #pragma unroll
        for (int z = 0; z < 3; z++)
            #pragma unroll
            for (int nt = 0; nt < 4; nt++) {
                float b0 = bias0[z][nt][0], b1 = bias0[z][nt][1];
                c0[z][nt][0] = b0; c0[z][nt][1] = b1; c0[z][nt][2] = b0; c0[z][nt][3] = b1;
                c1[z][nt][0] = b0; c1[z][nt][1] = b1; c1[z][nt][2] = b0; c1[z][nt][3] = b1;
            }

        const int a0_base = mt0  * 8 * 32 + lane;
        const int a1_base = mt1c * 8 * 32 + lane;

        #pragma unroll
        for (int ks = 0; ks < 8; ks++) {
            uint4 aA = g_hf[a0_base + ks * 32];
            uint4 aB = g_hf[a1_base + ks * 32];
            #pragma unroll
            for (int z = 0; z < 3; z++) {
                int bidx = ((z * 8 + ks) * 4 + w) * 64 + lane;
                uint4 bp0 = s_wf[bidx];
                uint4 bp1 = s_wf[bidx + 32];
                mma_f16(c0[z][0][0], c0[z][0][1], c0[z][0][2], c0[z][0][3],
                        aA.x, aA.y, aA.z, aA.w, bp0.x, bp0.y);
                mma_f16(c0[z][1][0], c0[z][1][1], c0[z][1][2], c0[z][1][3],
                        aA.x, aA.y, aA.z, aA.w, bp0.z, bp0.w);
                mma_f16(c0[z][2][0], c0[z][2][1], c0[z][2][2], c0[z][2][3],
                        aA.x, aA.y, aA.z, aA.w, bp1.x, bp1.y);
                mma_f16(c0[z][3][0], c0[z][3][1], c0[z][3][2], c0[z][3][3],
                        aA.x, aA.y, aA.z, aA.w, bp1.z, bp1.w);
                mma_f16(c1[z][0][0], c1[z][0][1], c1[z][0][2], c1[z][0][3],
                        aB.x, aB.y, aB.z, aB.w, bp0.x, bp0.y);
                mma_f16(c1[z][1][0], c1[z][1][1], c1[z][1][2], c1[z][1][3],
                        aB.x, aB.y, aB.z, aB.w, bp0.z, bp0.w);
                mma_f16(c1[z][2][0], c1[z][2][1], c1[z][2][2], c1[z][2][3],
                        aB.x, aB.y, aB.z, aB.w, bp1.x, bp1.y);
                mma_f16(c1[z][3][0], c1[z][3][1], c1[z][3][2], c1[z][3][3],
                        aB.x, aB.y, aB.z, aB.w, bp1.z, bp1.w);
            }
        }

        // ---- epilogue m-tile 0 ----
        {
            int m0 = mt0 * 16;
            #pragma unroll
            for (int nt = 0; nt < 4; nt++) {
                int col = (w * 4 + nt) * 8 + t * 2;
                *reinterpret_cast<float2*>(&g_Q[(m0 + g) * 128 + col])     = make_float2(c0[0][nt][0], c0[0][nt][1]);
                *reinterpret_cast<float2*>(&g_Q[(m0 + g + 8) * 128 + col]) = make_float2(c0[0][nt][2], c0[0][nt][3]);
                uint32_t klo = pack_h2(c0[1][nt][0], c0[1][nt][1]);
                uint32_t khi = pack_h2(c0[1][nt][2], c0[1][nt][3]);
                uint32_t vlo = pack_h2(c0[2][nt][0], c0[2][nt][1]);
                uint32_t vhi = pack_h2(c0[2][nt][2], c0[2][nt][3]);
                int j = col / 2;
                int slot = (j >> 1) * 4 + (j & 1);
                g_KV[(m0 + g) * 128 + slot]         = klo;
                g_KV[(m0 + g + 8) * 128 + slot]     = khi;
                g_KV[(m0 + g) * 128 + slot + 2]     = vlo;
                g_KV[(m0 + g + 8) * 128 + slot + 2] = vhi;
            }
        }
        // ---- epilogue m-tile 1 (guarded) ----
        if (has2) {
            int m0 = mt1 * 16;
            #pragma unroll
            for (int nt = 0; nt < 4; nt++) {
                int col = (w * 4 + nt) * 8 + t * 2;
                *reinterpret_cast<float2*>(&g_Q[(m0 + g) * 128 + col])     = make_float2(c1[0][nt][0], c1[0][nt][1]);
                *reinterpret_cast<float2*>(&g_Q[(m0 + g + 8) * 128 + col]) = make_float2(c1[0][nt][2], c1[0][nt][3]);
                uint32_t klo = pack_h2(c1[1][nt][0], c1[1][nt][1]);
                uint32_t khi = pack_h2(c1[1][nt][2], c1[1][nt][3]);
                uint32_t vlo = pack_h2(c1[2][nt][0], c1[2][nt][1]);
                uint32_t vhi = pack_h2(c1[2][nt][2], c1[2][nt][3]);
                int j = col / 2;
                int slot = (j >> 1) * 4 + (j & 1);
                g_KV[(m0 + g) * 128 + slot]         = klo;
                g_KV[(m0 + g + 8) * 128 + slot]     = khi;
                g_KV[(m0 + g) * 128 + slot + 2]     = vlo;
                g_KV[(m0 + g + 8) * 128 + slot + 2] = vhi;
            }
        }
    }
}

// ---------------- parallel scan, stage 1 ----------------
__global__ void __launch_bounds__(256) scan_part_kernel()
{
    __shared__ int ws[8];
    int gid = blockIdx.x * 256 + threadIdx.x;
    int v = (gid < N_NODES) ? g_cnt[gid] : 0;
    int s = __reduce_add_sync(0xffffffffu, v);
    if ((threadIdx.x & 31) == 0) ws[threadIdx.x >> 5] = s;
    __syncthreads();
    if (threadIdx.x == 0) {
        int tot = 0;
        #pragma unroll
        for (int j = 0; j < 8; j++) tot += ws[j];
        g_part[blockIdx.x] = tot;
    }
}

// ---------------- parallel scan, stage 2 ----------------
__global__ void __launch_bounds__(256) scan_final_kernel()
{
    __shared__ int ps[8];
    __shared__ int ws[8];
    const int t = threadIdx.x, b = blockIdx.x;
    const int lane = t & 31, w = t >> 5;

    int pv = (t < b) ? g_part[t] : 0;
    int psum = __reduce_add_sync(0xffffffffu, pv);
    if (lane == 0) ps[w] = psum;
    __syncthreads();
    int offset = 0;
    #pragma unroll
    for (int j = 0; j < 8; j++) offset += ps[j];

    int gid = b * 256 + t;
    int c = (gid < N_NODES) ? g_cnt[gid] : 0;
    int incl = c;
    #pragma unroll
    for (int d = 1; d < 32; d <<= 1) {
        int u = __shfl_up_sync(0xffffffffu, incl, d);
        if (lane >= d) incl += u;
    }
    if (lane == 31) ws[w] = incl;
    __syncthreads();
    int woff = 0;
    #pragma unroll
    for (int j = 0; j < 8; j++) woff += (j < w) ? ws[j] : 0;

    int excl = offset + woff + incl - c;
    if (gid < N_NODES) {
        g_row_off[gid] = excl;
        g_cnt[gid]     = excl;           // cursor for scatter
    }
    if (gid == N_NODES - 1)
        g_row_off[N_NODES] = excl + c;
}

// ---------------- aggregation: one warp per dst node, 2-edge software pipeline ----------------
// lane l owns columns 4l..4l+3; each 4-lane quad owns one head (D=16).
__global__ void __launch_bounds__(256) aggregate_kernel(float* __restrict__ out)
{
    int warp = (blockIdx.x * blockDim.x + threadIdx.x) >> 5;
    int lane = threadIdx.x & 31;
    if (warp >= N_NODES) return;
    const int node = warp;

    const float4 q = *reinterpret_cast<const float4*>(&g_Q[node * 128 + lane * 4]);
    float4 acc0 = make_float4(0.f, 0.f, 0.f, 0.f);
    float4 acc1 = make_float4(0.f, 0.f, 0.f, 0.f);
    float  zz0 = 0.f, zz1 = 0.f;

    const int beg = g_row_off[node];
    const int end = g_row_off[node + 1];
    int i = beg;

    for (; i + 2 <= end; i += 2) {
        int s0 = g_esrc[i];
        int s1 = g_esrc[i + 1];
        uint4 kv0 = *reinterpret_cast<const uint4*>(&g_KV[s0 * 128 + lane * 4]);
        uint4 kv1 = *reinterpret_cast<const uint4*>(&g_KV[s1 * 128 + lane * 4]);

        float2 k0a = __half22float2(*reinterpret_cast<__half2*>(&kv0.x));
        float2 k0b = __half22float2(*reinterpret_cast<__half2*>(&kv0.y));
        float2 k1a = __half22float2(*reinterpret_cast<__half2*>(&kv1.x));
        float2 k1b = __half22float2(*reinterpret_cast<__half2*>(&kv1.y));

        float p0 = q.x * k0a.x + q.y * k0a.y + q.z * k0b.x + q.w * k0b.y;
        float p1 = q.x * k1a.x + q.y * k1a.y + q.z * k1b.x + q.w * k1b.y;
        p0 += __shfl_xor_sync(0xffffffffu, p0, 1);
        p1 += __shfl_xor_sync(0xffffffffu, p1, 1);
        p0 += __shfl_xor_sync(0xffffffffu, p0, 2);
        p1 += __shfl_xor_sync(0xffffffffu, p1, 2);

        float w0 = __expf(fminf(fmaxf(p0 * 0.25f, -5.f), 5.f));
        float w1 = __expf(fminf(fmaxf(p1 * 0.25f, -5.f), 5.f));

        float2 v0a = __half22float2(*reinterpret_cast<__half2*>(&kv0.z));
        float2 v0b = __half22float2(*reinterpret_cast<__half2*>(&kv0.w));
        float2 v1a = __half22float2(*reinterpret_cast<__half2*>(&kv1.z));
        float2 v1b = __half22float2(*reinterpret_cast<__half2*>(&kv1.w));

        acc0.x += v0a.x * w0;  acc0.y += v0a.y * w0;
        acc0.z += v0b.x * w0;  acc0.w += v0b.y * w0;
        acc1.x += v1a.x * w1;  acc1.y += v1a.y * w1;
        acc1.z += v1b.x * w1;  acc1.w += v1b.y * w1;
        zz0 += w0;
        zz1 += w1;
    }

    if (i < end) {
        int s = g_esrc[i];
        uint4 kv = *reinterpret_cast<const uint4*>(&g_KV[s * 128 + lane * 4]);
        float2 ka = __half22float2(*reinterpret_cast<__half2*>(&kv.x));
        float2 kb = __half22float2(*reinterpret_cast<__half2*>(&kv.y));
        float p = q.x * ka.x + q.y * ka.y + q.z * kb.x + q.w * kb.y;
        p += __shfl_xor_sync(0xffffffffu, p, 1);
        p += __shfl_xor_sync(0xffffffffu, p, 2);
        float wgt = __expf(fminf(fmaxf(p * 0.25f, -5.f), 5.f));
        float2 va = __half22float2(*reinterpret_cast<__half2*>(&kv.z));
        float2 vb = __half22float2(*reinterpret_cast<__half2*>(&kv.w));
        acc0.x += va.x * wgt;  acc0.y += va.y * wgt;
        acc0.z += vb.x * wgt;  acc0.w += vb.y * wgt;
        zz0 += wgt;
    }

    float inv = 1.f / (zz0 + zz1 + 1e-6f);
    float4 o = make_float4((acc0.x + acc1.x) * inv, (acc0.y + acc1.y) * inv,
                           (acc0.z + acc1.z) * inv, (acc0.w + acc1.w) * inv);
    *reinterpret_cast<float4*>(&out[node * 128 + lane * 4]) = o;

    if (lane == 0) g_cnt[node] = 0;                 // restore invariant for next launch
}

// ---------------- launch ----------------
extern "C" void kernel_launch(void* const* d_in, const int* in_sizes, int n_in,
                              void* d_out, int out_size)
{
    const float* h   = (const float*)d_in[0];
    // d_in[1] (e), d_in[8] (We), d_in[9] (be) are unused by the reference output.
    const int*   src = (const int*)d_in[2];
    const int*   dst = (const int*)d_in[3];
    const float* Wq  = (const float*)d_in[4];
    const float* bq  = (const float*)d_in[5];
    const float* Wk  = (const float*)d_in[6];
    const float* bk  = (const float*)d_in[7];
    const float* Wv  = (const float*)d_in[10];
    const float* bv  = (const float*)d_in[11];
    float* out = (float*)d_out;

    dim3 prep_grid(M_TILES, 1, 3);  // z=0: A-frag pack (800k threads), z=1: count, z=2: B frags
    prep_kernel<<<prep_grid, 256>>>(h, dst, Wq, Wk, Wv);

    scan_part_kernel<<<SCAN_BLOCKS, 256>>>();
    scan_final_kernel<<<SCAN_BLOCKS, 256>>>();

    cudaFuncSetAttribute(gemm_scatter, cudaFuncAttributeMaxDynamicSharedMemorySize, SMEM_B_BYTES);
    gemm_scatter<<<P_CTAS, 256, SMEM_B_BYTES>>>(bq, bk, bv, src, dst);

    int agg_blocks = (N_NODES + 7) / 8;   // 8 warps (nodes) per 256-thread block
    aggregate_kernel<<<agg_blocks, 256>>>(out);
}